// round 1
// baseline (speedup 1.0000x reference)
#include <cuda_runtime.h>
#include <cstddef>

#define TSTEPS 1024
#define BATCH  128
#define DIN    64
#define HH     512
#define NTHR   512
#define EPSF   1e-5f

__device__ __forceinline__ void fma4(float4& a, float h, const float4 w) {
    a.x = fmaf(h, w.x, a.x);
    a.y = fmaf(h, w.y, a.y);
    a.z = fmaf(h, w.z, a.z);
    a.w = fmaf(h, w.w, a.w);
}

// Accumulate a K=512 GEMV slice for this thread's 4 columns (cg) and k-phase p,
// for two batch rows at once (h vectors live in shared memory).
__device__ __forceinline__ void gemv512(const float* __restrict__ W,
                                        const float* hrow0, const float* hrow1,
                                        int p, int cg, float4& a0, float4& a1) {
    const float* Wq = W + (size_t)(p * 128) * HH + 4 * cg;
    const float4* hh0 = (const float4*)(hrow0 + p * 128);
    const float4* hh1 = (const float4*)(hrow1 + p * 128);
#pragma unroll 4
    for (int m = 0; m < 32; ++m) {
        float4 h0v = hh0[m];
        float4 h1v = hh1[m];
        const float* wb = Wq + (size_t)(4 * m) * HH;
        float4 w0 = *(const float4*)(wb);
        float4 w1 = *(const float4*)(wb + HH);
        float4 w2 = *(const float4*)(wb + 2 * HH);
        float4 w3 = *(const float4*)(wb + 3 * HH);
        fma4(a0, h0v.x, w0); fma4(a1, h1v.x, w0);
        fma4(a0, h0v.y, w1); fma4(a1, h1v.y, w1);
        fma4(a0, h0v.z, w2); fma4(a1, h1v.z, w2);
        fma4(a0, h0v.w, w3); fma4(a1, h1v.w, w3);
    }
}

__global__ void __launch_bounds__(NTHR, 1)
rnn_forecaster_kernel(
    const float* __restrict__ x,
    const float* __restrict__ Wi0, const float* __restrict__ bi0,
    const float* __restrict__ Wh0, const float* __restrict__ bh0,
    const float* __restrict__ g0,  const float* __restrict__ be0,
    const float* __restrict__ Wi1, const float* __restrict__ bi1,
    const float* __restrict__ Wh1, const float* __restrict__ bh1,
    const float* __restrict__ g1,  const float* __restrict__ be1,
    const float* __restrict__ Wfc, const float* __restrict__ bfc,
    float* __restrict__ out)
{
    __shared__ float sh0[2][HH];          // layer-0 hidden state, 2 rows
    __shared__ float sh1[2][HH];          // layer-1 hidden state, 2 rows
    __shared__ float scb0[HH], scb1[HH];  // combined biases bi+bh
    __shared__ float sg0[HH], sbe0[HH], sg1[HH], sbe1[HH];
    __shared__ float sx[2][DIN];          // x_t for both rows
    __shared__ float red[4][128][8];      // k-phase partial sums
    __shared__ float wred[16][4];         // per-warp LN partials
    __shared__ float bc[2][2];            // (mu, rstd) per row

    const int tid  = threadIdx.x;
    const int cg   = tid & 127;   // column group: cols 4cg..4cg+3
    const int p    = tid >> 7;    // k-phase 0..3
    const int lane = tid & 31;
    const int wid  = tid >> 5;
    const int row0 = blockIdx.x * 2;
    const int j    = tid;         // column this thread owns post-reduction
    const int cg2  = j >> 2, cc = j & 3;

    for (int i = tid; i < HH; i += NTHR) {
        scb0[i] = bi0[i] + bh0[i];
        scb1[i] = bi1[i] + bh1[i];
        sg0[i] = g0[i];  sbe0[i] = be0[i];
        sg1[i] = g1[i];  sbe1[i] = be1[i];
        sh0[0][i] = 0.f; sh0[1][i] = 0.f;
        sh1[0][i] = 0.f; sh1[1][i] = 0.f;
    }
    __syncthreads();

    for (int t = 0; t < TSTEPS; ++t) {
        // stage x_t for both rows
        if (tid < 2 * DIN) {
            int r = tid >> 6, k = tid & 63;
            sx[r][k] = x[((size_t)(row0 + r) * TSTEPS + t) * DIN + k];
        }
        __syncthreads();

        // ================= layer 0 =================
        float4 a0 = make_float4(0.f, 0.f, 0.f, 0.f);
        float4 a1 = make_float4(0.f, 0.f, 0.f, 0.f);
        {
            // x_t @ Wi0 (K = 64 -> 16 k per phase)
            const float* Wp = Wi0 + (size_t)(p * 16) * HH + 4 * cg;
            const float4* hx0 = (const float4*)&sx[0][p * 16];
            const float4* hx1 = (const float4*)&sx[1][p * 16];
#pragma unroll
            for (int m = 0; m < 4; ++m) {
                float4 h0v = hx0[m];
                float4 h1v = hx1[m];
                const float* wb = Wp + (size_t)(4 * m) * HH;
                float4 w0 = *(const float4*)(wb);
                float4 w1 = *(const float4*)(wb + HH);
                float4 w2 = *(const float4*)(wb + 2 * HH);
                float4 w3 = *(const float4*)(wb + 3 * HH);
                fma4(a0, h0v.x, w0); fma4(a1, h1v.x, w0);
                fma4(a0, h0v.y, w1); fma4(a1, h1v.y, w1);
                fma4(a0, h0v.z, w2); fma4(a1, h1v.z, w2);
                fma4(a0, h0v.w, w3); fma4(a1, h1v.w, w3);
            }
            // h0 @ Wh0 (K = 512)
            gemv512(Wh0, &sh0[0][0], &sh0[1][0], p, cg, a0, a1);
        }
        *(float4*)&red[p][cg][0] = a0;
        *(float4*)&red[p][cg][4] = a1;
        __syncthreads();
        {
            float z0 = red[0][cg2][cc] + red[1][cg2][cc] + red[2][cg2][cc] + red[3][cg2][cc] + scb0[j];
            float z1 = red[0][cg2][4 + cc] + red[1][cg2][4 + cc] + red[2][cg2][4 + cc] + red[3][cg2][4 + cc] + scb0[j];
            float c0 = tanhf(z0) + sh0[0][j];
            float c1 = tanhf(z1) + sh0[1][j];
            float s0 = c0, s1 = c1, q0 = c0 * c0, q1 = c1 * c1;
#pragma unroll
            for (int o = 16; o; o >>= 1) {
                s0 += __shfl_xor_sync(0xffffffffu, s0, o);
                s1 += __shfl_xor_sync(0xffffffffu, s1, o);
                q0 += __shfl_xor_sync(0xffffffffu, q0, o);
                q1 += __shfl_xor_sync(0xffffffffu, q1, o);
            }
            if (lane == 0) { wred[wid][0] = s0; wred[wid][1] = s1; wred[wid][2] = q0; wred[wid][3] = q1; }
            __syncthreads();
            if (wid == 0) {
                float v0 = (lane < 16) ? wred[lane][0] : 0.f;
                float v1 = (lane < 16) ? wred[lane][1] : 0.f;
                float v2 = (lane < 16) ? wred[lane][2] : 0.f;
                float v3 = (lane < 16) ? wred[lane][3] : 0.f;
#pragma unroll
                for (int o = 8; o; o >>= 1) {
                    v0 += __shfl_xor_sync(0xffffffffu, v0, o);
                    v1 += __shfl_xor_sync(0xffffffffu, v1, o);
                    v2 += __shfl_xor_sync(0xffffffffu, v2, o);
                    v3 += __shfl_xor_sync(0xffffffffu, v3, o);
                }
                if (lane == 0) {
                    float mu0 = v0 * (1.f / HH), mu1 = v1 * (1.f / HH);
                    float var0 = v2 * (1.f / HH) - mu0 * mu0;
                    float var1 = v3 * (1.f / HH) - mu1 * mu1;
                    bc[0][0] = mu0; bc[0][1] = rsqrtf(var0 + EPSF);
                    bc[1][0] = mu1; bc[1][1] = rsqrtf(var1 + EPSF);
                }
            }
            __syncthreads();
            sh0[0][j] = (c0 - bc[0][0]) * bc[0][1] * sg0[j] + sbe0[j];
            sh0[1][j] = (c1 - bc[1][0]) * bc[1][1] * sg0[j] + sbe0[j];
        }
        __syncthreads();

        // ================= layer 1 =================
        a0 = make_float4(0.f, 0.f, 0.f, 0.f);
        a1 = make_float4(0.f, 0.f, 0.f, 0.f);
        gemv512(Wi1, &sh0[0][0], &sh0[1][0], p, cg, a0, a1);  // h0n @ Wi1
        gemv512(Wh1, &sh1[0][0], &sh1[1][0], p, cg, a0, a1);  // h1  @ Wh1
        *(float4*)&red[p][cg][0] = a0;
        *(float4*)&red[p][cg][4] = a1;
        __syncthreads();
        {
            float z0 = red[0][cg2][cc] + red[1][cg2][cc] + red[2][cg2][cc] + red[3][cg2][cc] + scb1[j];
            float z1 = red[0][cg2][4 + cc] + red[1][cg2][4 + cc] + red[2][cg2][4 + cc] + red[3][cg2][4 + cc] + scb1[j];
            float c0 = tanhf(z0) + sh1[0][j];
            float c1 = tanhf(z1) + sh1[1][j];
            float s0 = c0, s1 = c1, q0 = c0 * c0, q1 = c1 * c1;
#pragma unroll
            for (int o = 16; o; o >>= 1) {
                s0 += __shfl_xor_sync(0xffffffffu, s0, o);
                s1 += __shfl_xor_sync(0xffffffffu, s1, o);
                q0 += __shfl_xor_sync(0xffffffffu, q0, o);
                q1 += __shfl_xor_sync(0xffffffffu, q1, o);
            }
            if (lane == 0) { wred[wid][0] = s0; wred[wid][1] = s1; wred[wid][2] = q0; wred[wid][3] = q1; }
            __syncthreads();
            if (wid == 0) {
                float v0 = (lane < 16) ? wred[lane][0] : 0.f;
                float v1 = (lane < 16) ? wred[lane][1] : 0.f;
                float v2 = (lane < 16) ? wred[lane][2] : 0.f;
                float v3 = (lane < 16) ? wred[lane][3] : 0.f;
#pragma unroll
                for (int o = 8; o; o >>= 1) {
                    v0 += __shfl_xor_sync(0xffffffffu, v0, o);
                    v1 += __shfl_xor_sync(0xffffffffu, v1, o);
                    v2 += __shfl_xor_sync(0xffffffffu, v2, o);
                    v3 += __shfl_xor_sync(0xffffffffu, v3, o);
                }
                if (lane == 0) {
                    float mu0 = v0 * (1.f / HH), mu1 = v1 * (1.f / HH);
                    float var0 = v2 * (1.f / HH) - mu0 * mu0;
                    float var1 = v3 * (1.f / HH) - mu1 * mu1;
                    bc[0][0] = mu0; bc[0][1] = rsqrtf(var0 + EPSF);
                    bc[1][0] = mu1; bc[1][1] = rsqrtf(var1 + EPSF);
                }
            }
            __syncthreads();
            sh1[0][j] = (c0 - bc[0][0]) * bc[0][1] * sg1[j] + sbe1[j];
            sh1[1][j] = (c1 - bc[1][0]) * bc[1][1] * sg1[j] + sbe1[j];
        }
        __syncthreads();
    }

    // ======== output head: out[b] = h1[b] . Wfc + bfc ========
    {
        float v0 = sh1[0][j] * Wfc[j];
        float v1 = sh1[1][j] * Wfc[j];
#pragma unroll
        for (int o = 16; o; o >>= 1) {
            v0 += __shfl_xor_sync(0xffffffffu, v0, o);
            v1 += __shfl_xor_sync(0xffffffffu, v1, o);
        }
        if (lane == 0) { wred[wid][0] = v0; wred[wid][1] = v1; }
        __syncthreads();
        if (wid == 0) {
            float u0 = (lane < 16) ? wred[lane][0] : 0.f;
            float u1 = (lane < 16) ? wred[lane][1] : 0.f;
#pragma unroll
            for (int o = 8; o; o >>= 1) {
                u0 += __shfl_xor_sync(0xffffffffu, u0, o);
                u1 += __shfl_xor_sync(0xffffffffu, u1, o);
            }
            if (lane == 0) {
                float b = bfc[0];
                out[row0]     = u0 + b;
                out[row0 + 1] = u1 + b;
            }
        }
    }
}

extern "C" void kernel_launch(void* const* d_in, const int* in_sizes, int n_in,
                              void* d_out, int out_size) {
    (void)in_sizes; (void)n_in; (void)out_size;
    const float* x   = (const float*)d_in[0];
    const float* Wi0 = (const float*)d_in[1];
    const float* bi0 = (const float*)d_in[2];
    const float* Wh0 = (const float*)d_in[3];
    const float* bh0 = (const float*)d_in[4];
    const float* g0  = (const float*)d_in[5];
    const float* be0 = (const float*)d_in[6];
    const float* Wi1 = (const float*)d_in[7];
    const float* bi1 = (const float*)d_in[8];
    const float* Wh1 = (const float*)d_in[9];
    const float* bh1 = (const float*)d_in[10];
    const float* g1  = (const float*)d_in[11];
    const float* be1 = (const float*)d_in[12];
    const float* Wfc = (const float*)d_in[13];
    const float* bfc = (const float*)d_in[14];

    rnn_forecaster_kernel<<<BATCH / 2, NTHR>>>(
        x, Wi0, bi0, Wh0, bh0, g0, be0,
        Wi1, bi1, Wh1, bh1, g1, be1,
        Wfc, bfc, (float*)d_out);
}